// round 16
// baseline (speedup 1.0000x reference)
#include <cuda_runtime.h>
#include <cuda_bf16.h>
#include <math.h>
#include <stdint.h>

// ---------------- problem constants ----------------
#define DIM   256
#define HEADS 8
#define HD    32
#define PL    8
#define LAT   60
#define LON   120
#define WPL   2
#define WLAT  6
#define WLON  12
#define NTOK  144
#define NPL   (PL/WPL)
#define NLAT  (LAT/WLAT)
#define NLON  (LON/WLON)
#define NW    (NPL*NLAT)     // 40
#define BATCH 2
#define LTOK  (PL*LAT*LON)   // 57600
#define MTOK  (BATCH*LTOK)   // 115200
#define HID   1024
#define TBL   3312

typedef __nv_bfloat16 bf16;

// ---------------- scratch ----------------
__device__ bf16  g_hw  [(size_t)MTOK*DIM];
__device__ bf16  g_qkv [(size_t)MTOK*3*DIM];
__device__ bf16  g_attn[(size_t)MTOK*DIM];
__device__ float g_x2  [(size_t)MTOK*DIM];
__device__ bf16  g_ln2 [(size_t)MTOK*DIM];
__device__ bf16  g_fc1 [(size_t)MTOK*HID];
__device__ bf16  g_wqkv [3*DIM*DIM];
__device__ bf16  g_wproj[DIM*DIM];
__device__ bf16  g_wfc1 [HID*DIM];
__device__ bf16  g_wfc2 [DIM*HID];
__device__ float g_bt  [NW*HEADS*TBL];

// ---------------- helpers ----------------
__device__ __forceinline__ int win_index(int t) {
    int b   = t / LTOK;
    int rem = t - b * LTOK;
    int pl  = rem / (LAT * LON);
    int r2  = rem - pl * (LAT * LON);
    int lat = r2 / LON;
    int lon = r2 - lat * LON;
    int np = pl / WPL,  ip = pl - np * WPL;
    int nl = lat / WLAT, il = lat - nl * WLAT;
    int no = lon / WLON, io = lon - no * WLON;
    int wb = b * NLON + no;
    int w  = np * NLAT + nl;
    int n  = (ip * WLAT + il) * WLON + io;
    return (wb * NW + w) * NTOK + n;
}
__device__ __forceinline__ int inv_win_index(int wi) {
    int n  = wi % NTOK;
    int w  = (wi / NTOK) % NW;
    int wb = wi / (NTOK * NW);
    int b  = wb / NLON, no = wb % NLON;
    int np = w / NLAT,  nl = w % NLAT;
    int ip = n / (WLAT * WLON);
    int il = (n / WLON) % WLAT;
    int io = n % WLON;
    int pl  = np * WPL + ip;
    int lat = nl * WLAT + il;
    int lon = no * WLON + io;
    return b * LTOK + (pl * LAT + lat) * LON + lon;
}
__device__ __forceinline__ void warp_reduce2(float& a, float& b) {
    #pragma unroll
    for (int o = 16; o > 0; o >>= 1) {
        a += __shfl_xor_sync(0xffffffffu, a, o);
        b += __shfl_xor_sync(0xffffffffu, b, o);
    }
}

// ---------------- setup: fused weight conversion + bias transpose ----------------
#define NQ4  (3*DIM*DIM/4)   // 49152
#define NP4  (DIM*DIM/4)     // 16384
#define NF14 (HID*DIM/4)     // 65536
#define NF24 (DIM*HID/4)     // 65536
#define NTOT4 (NQ4+NP4+NF14+NF24)   // 196608

__global__ void wconv_kernel(const float* __restrict__ qkv_w,
                             const float* __restrict__ proj_w,
                             const float* __restrict__ fc1_w,
                             const float* __restrict__ fc2_w) {
    int i = blockIdx.x * blockDim.x + threadIdx.x;
    if (i >= NTOT4) return;
    const float* src;
    bf16* dst;
    int j = i;
    if (j < NQ4)                    { src = qkv_w;  dst = g_wqkv;  }
    else if ((j -= NQ4)  < NP4)     { src = proj_w; dst = g_wproj; }
    else if ((j -= NP4)  < NF14)    { src = fc1_w;  dst = g_wfc1;  }
    else { j -= NF14;                 src = fc2_w;  dst = g_wfc2;  }
    float4 v = *(const float4*)&src[j * 4];
    *(__nv_bfloat162*)&dst[j * 4]     = __floats2bfloat162_rn(v.x, v.y);
    *(__nv_bfloat162*)&dst[j * 4 + 2] = __floats2bfloat162_rn(v.z, v.w);
}
__global__ void bt_kernel(const float* __restrict__ src) {
    int c   = blockIdx.y;
    int idx = blockIdx.x * 256 + threadIdx.x;
    if (idx < TBL)
        g_bt[c * TBL + idx] = __ldg(&src[(size_t)idx * (NW * HEADS) + c]);
}

// ---------------- LN1: warp per token, bf16 scatter ----------------
__global__ __launch_bounds__(256)
void ln1_kernel(const float* __restrict__ x,
                const float* __restrict__ g,
                const float* __restrict__ b) {
    int warp = threadIdx.x >> 5, lane = threadIdx.x & 31;
    int t = blockIdx.x * 8 + warp;
    const float4* xr = (const float4*)(x + (size_t)t * DIM);
    float4 u0 = xr[lane], u1 = xr[lane + 32];
    float s = u0.x + u0.y + u0.z + u0.w + u1.x + u1.y + u1.z + u1.w;
    float q = u0.x*u0.x + u0.y*u0.y + u0.z*u0.z + u0.w*u0.w
            + u1.x*u1.x + u1.y*u1.y + u1.z*u1.z + u1.w*u1.w;
    warp_reduce2(s, q);
    float mu  = s * (1.0f / DIM);
    float var = q * (1.0f / DIM) - mu * mu;
    float rs  = rsqrtf(fmaxf(var, 0.f) + 1e-5f);
    float4 g0 = ((const float4*)g)[lane], g1 = ((const float4*)g)[lane + 32];
    float4 b0 = ((const float4*)b)[lane], b1 = ((const float4*)b)[lane + 32];
    int wi = win_index(t);
    __nv_bfloat162* dst = (__nv_bfloat162*)(g_hw + (size_t)wi * DIM);
    dst[lane * 2]          = __floats2bfloat162_rn((u0.x - mu) * rs * g0.x + b0.x,
                                                   (u0.y - mu) * rs * g0.y + b0.y);
    dst[lane * 2 + 1]      = __floats2bfloat162_rn((u0.z - mu) * rs * g0.z + b0.z,
                                                   (u0.w - mu) * rs * g0.w + b0.w);
    dst[64 + lane * 2]     = __floats2bfloat162_rn((u1.x - mu) * rs * g1.x + b1.x,
                                                   (u1.y - mu) * rs * g1.y + b1.y);
    dst[64 + lane * 2 + 1] = __floats2bfloat162_rn((u1.z - mu) * rs * g1.z + b1.z,
                                                   (u1.w - mu) * rs * g1.w + b1.w);
}

// ---------------- LN2 over token-ordered x2 ----------------
__global__ __launch_bounds__(256)
void ln2_kernel(const float* __restrict__ g,
                const float* __restrict__ b) {
    int warp = threadIdx.x >> 5, lane = threadIdx.x & 31;
    int t = blockIdx.x * 8 + warp;
    const float4* xr = (const float4*)(g_x2 + (size_t)t * DIM);
    float4 u0 = xr[lane], u1 = xr[lane + 32];
    float s = u0.x + u0.y + u0.z + u0.w + u1.x + u1.y + u1.z + u1.w;
    float q = u0.x*u0.x + u0.y*u0.y + u0.z*u0.z + u0.w*u0.w
            + u1.x*u1.x + u1.y*u1.y + u1.z*u1.z + u1.w*u1.w;
    warp_reduce2(s, q);
    float mu  = s * (1.0f / DIM);
    float var = q * (1.0f / DIM) - mu * mu;
    float rs  = rsqrtf(fmaxf(var, 0.f) + 1e-5f);
    float4 g0 = ((const float4*)g)[lane], g1 = ((const float4*)g)[lane + 32];
    float4 b0 = ((const float4*)b)[lane], b1 = ((const float4*)b)[lane + 32];
    __nv_bfloat162* dst = (__nv_bfloat162*)(g_ln2 + (size_t)t * DIM);
    dst[lane * 2]          = __floats2bfloat162_rn((u0.x - mu) * rs * g0.x + b0.x,
                                                   (u0.y - mu) * rs * g0.y + b0.y);
    dst[lane * 2 + 1]      = __floats2bfloat162_rn((u0.z - mu) * rs * g0.z + b0.z,
                                                   (u0.w - mu) * rs * g0.w + b0.w);
    dst[64 + lane * 2]     = __floats2bfloat162_rn((u1.x - mu) * rs * g1.x + b1.x,
                                                   (u1.y - mu) * rs * g1.y + b1.y);
    dst[64 + lane * 2 + 1] = __floats2bfloat162_rn((u1.z - mu) * rs * g1.z + b1.z,
                                                   (u1.w - mu) * rs * g1.w + b1.w);
}

// ---------------- bf16 GEMM: BM=BN=128, BK=64, 3-stage, 2 CTAs/SM ----------------
#define BK2  64
#define SAS2 72
#define STG2 (128 * SAS2 * 2)          // 18432 B
#define NSTG 3
#define GEMM_SMEM (2 * NSTG * STG2)    // 110592 B

__device__ __forceinline__ void cp16(uint32_t smem_addr, const void* gmem_src) {
    asm volatile("cp.async.cg.shared.global [%0], [%1], 16;\n" :: "r"(smem_addr), "l"(gmem_src));
}
__device__ __forceinline__ void ldsm_x4(uint32_t& r0, uint32_t& r1, uint32_t& r2, uint32_t& r3,
                                        uint32_t addr) {
    asm volatile("ldmatrix.sync.aligned.m8n8.x4.shared.b16 {%0,%1,%2,%3}, [%4];"
                 : "=r"(r0), "=r"(r1), "=r"(r2), "=r"(r3) : "r"(addr));
}

template<bool GELU, bool RES, bool OBF, bool WREV>
__global__ __launch_bounds__(256, 2)
void bgemm_kernel(const bf16* __restrict__ A,
                  const bf16* __restrict__ W,
                  const float* __restrict__ bias,
                  const float* __restrict__ res,
                  void* __restrict__ Cv,
                  int M, int N, int K) {
    extern __shared__ bf16 smem[];

    int tid  = threadIdx.x;
    int bm   = blockIdx.y * 128;
    int bn   = blockIdx.x * 128;
    int warp = tid >> 5, lane = tid & 31;
    int wm = (warp & 3) * 32;
    int wn = (warp >> 2) * 64;
    int gID = lane >> 2;
    int tig = lane & 3;

    uint32_t aBase = (uint32_t)__cvta_generic_to_shared(&smem[0]);
    uint32_t bBase = aBase + NSTG * STG2;
    int seg = lane >> 3, ri = lane & 7;
    uint32_t aAddr = aBase + (uint32_t)(((wm + (seg & 1) * 8 + ri) * SAS2 + (seg >> 1) * 8) * 2);
    uint32_t bAddr = bBase + (uint32_t)(((wn + (seg >> 1) * 8 + ri) * SAS2 + (seg & 1) * 8) * 2);

    float acc[2][8][4];
    #pragma unroll
    for (int mt = 0; mt < 2; mt++)
        #pragma unroll
        for (int nt = 0; nt < 8; nt++)
            #pragma unroll
            for (int i = 0; i < 4; i++) acc[mt][nt][i] = 0.f;

    int niter = K / BK2;

    auto load_stage = [&](int s, int k0) {
        #pragma unroll
        for (int r4 = 0; r4 < 4; r4++) {
            int idx = tid + r4 * 256;
            int row = idx >> 3, c = idx & 7;
            uint32_t off = (uint32_t)s * STG2 + (uint32_t)((row * SAS2 + c * 8) * 2);
            cp16(aBase + off, &A[(size_t)(bm + row) * K + k0 + c * 8]);
            cp16(bBase + off, &W[(size_t)(bn + row) * K + k0 + c * 8]);
        }
        asm volatile("cp.async.commit_group;\n");
    };

    load_stage(0, 0);
    if (niter > 1) load_stage(1, BK2);
    if (niter > 2) load_stage(2, 2 * BK2);

    for (int it = 0; it < niter; it++) {
        int cur = it % NSTG;
        if (it + 3 <= niter)      asm volatile("cp.async.wait_group 2;\n");
        else if (it + 2 == niter) asm volatile("cp.async.wait_group 1;\n");
        else                      asm volatile("cp.async.wait_group 0;\n");
        __syncthreads();

        uint32_t aS = aAddr + (uint32_t)cur * STG2;
        uint32_t bS = bAddr + (uint32_t)cur * STG2;

        #pragma unroll
        for (int ks = 0; ks < 4; ks++) {
            uint32_t ko = ks * 32;
            uint32_t af[2][4];
            ldsm_x4(af[0][0], af[0][1], af[0][2], af[0][3], aS + ko);
            ldsm_x4(af[1][0], af[1][1], af[1][2], af[1][3], aS + 16 * SAS2 * 2 + ko);
            uint32_t bfr[8][2];
            #pragma unroll
            for (int p = 0; p < 4; p++) {
                ldsm_x4(bfr[2*p][0], bfr[2*p][1], bfr[2*p+1][0], bfr[2*p+1][1],
                        bS + (uint32_t)(p * 16 * SAS2 * 2) + ko);
            }
            #pragma unroll
            for (int mt = 0; mt < 2; mt++)
                #pragma unroll
                for (int nt = 0; nt < 8; nt++) {
                    asm volatile(
                        "mma.sync.aligned.m16n8k16.row.col.f32.bf16.bf16.f32 "
                        "{%0,%1,%2,%3}, {%4,%5,%6,%7}, {%8,%9}, {%0,%1,%2,%3};"
                        : "+f"(acc[mt][nt][0]), "+f"(acc[mt][nt][1]),
                          "+f"(acc[mt][nt][2]), "+f"(acc[mt][nt][3])
                        : "r"(af[mt][0]), "r"(af[mt][1]), "r"(af[mt][2]), "r"(af[mt][3]),
                          "r"(bfr[nt][0]), "r"(bfr[nt][1]));
                }
        }
        __syncthreads();
        if (it + 3 < niter) load_stage(cur, (it + 3) * BK2);
    }

    float* Cf = (float*)Cv;
    bf16*  Cb = (bf16*)Cv;
    #pragma unroll
    for (int mt = 0; mt < 2; mt++) {
        int r0 = bm + wm + mt * 16 + gID;
        int r1 = r0 + 8;
        int t0 = WREV ? inv_win_index(r0) : r0;
        int t1 = WREV ? inv_win_index(r1) : r1;
        #pragma unroll
        for (int nt = 0; nt < 8; nt++) {
            int c = bn + wn + nt * 8 + tig * 2;
            float b0 = bias[c], b1 = bias[c + 1];
            float v00 = acc[mt][nt][0] + b0;
            float v01 = acc[mt][nt][1] + b1;
            float v10 = acc[mt][nt][2] + b0;
            float v11 = acc[mt][nt][3] + b1;
            if (GELU) {
                v00 = 0.5f * v00 * (1.0f + erff(v00 * 0.70710678118654752f));
                v01 = 0.5f * v01 * (1.0f + erff(v01 * 0.70710678118654752f));
                v10 = 0.5f * v10 * (1.0f + erff(v10 * 0.70710678118654752f));
                v11 = 0.5f * v11 * (1.0f + erff(v11 * 0.70710678118654752f));
            }
            size_t o0 = (size_t)t0 * N + c;
            size_t o1 = (size_t)t1 * N + c;
            if (RES) {
                float2 q0 = *(const float2*)&res[o0];
                float2 q1 = *(const float2*)&res[o1];
                v00 += q0.x; v01 += q0.y; v10 += q1.x; v11 += q1.y;
            }
            if (OBF) {
                *(__nv_bfloat162*)&Cb[o0] = __floats2bfloat162_rn(v00, v01);
                *(__nv_bfloat162*)&Cb[o1] = __floats2bfloat162_rn(v10, v11);
            } else {
                *(float2*)&Cf[o0] = make_float2(v00, v01);
                *(float2*)&Cf[o1] = make_float2(v10, v11);
            }
        }
    }
}

// ---------------- windowed attention: bf16 QK^T + register-P bf16 PV ----------------
#define QKB  40
#define VTS  152

#define SQ_B   0
#define SK_B   (SQ_B + NTOK*QKB*2)
#define SVT_B  (SK_B + NTOK*QKB*2)
#define SB_B   (SVT_B + HD*VTS*2)
#define SI_B   (SB_B + TBL*4)
#define ATTN_SMEM_BYTES (SI_B + 288*4)

__global__ __launch_bounds__(288)
void attn_kernel() {
    extern __shared__ char smc[];
    bf16*  sq  = (bf16*)(smc + SQ_B);
    bf16*  sk  = (bf16*)(smc + SK_B);
    bf16*  svT = (bf16*)(smc + SVT_B);
    float* sb  = (float*)(smc + SB_B);
    int*   sri = (int*)(smc + SI_B);
    int*   scj = sri + NTOK;
    const uint32_t* sqU  = (const uint32_t*)sq;
    const uint32_t* skU  = (const uint32_t*)sk;
    const uint32_t* svTU = (const uint32_t*)svT;

    int wg = blockIdx.x;
    int h  = blockIdx.y;
    int wt = wg % NW;
    int tid = threadIdx.x;
    size_t base = (size_t)wg * NTOK;
    const float scale = 0.17677669529663687f;

    if (tid < NTOK) {
        int i = tid;
        sri[i] = (i / 72) * 828 + ((i / 12) % 6) * 23 + (i % 12);
    } else {
        int j = tid - NTOK;
        scj[j] = (j / 72) * 1656 + ((j / 12) % 6) * 138 + (11 - (j % 12));
    }

    {
        const float* bt = g_bt + (size_t)(wt * HEADS + h) * TBL;
        for (int idx = tid; idx < TBL; idx += 288)
            sb[idx] = __ldg(&bt[idx]);
    }

    for (int idx = tid; idx < NTOK * 4; idx += 288) {
        int n = idx >> 2, e8 = (idx & 3) * 8;
        size_t toff = (base + n) * (size_t)(3 * DIM) + h * HD + e8;
        uint4 qr = *(const uint4*)&g_qkv[toff];
        uint4 kr = *(const uint4*)&g_qkv[toff + DIM];
        uint4 vr = *(const uint4*)&g_qkv[toff + 2 * DIM];
        *(uint4*)&sq[n * QKB + e8] = qr;
        *(uint4*)&sk[n * QKB + e8] = kr;
        const bf16* vb = (const bf16*)&vr;
        #pragma unroll
        for (int p = 0; p < 8; p++)
            svT[(e8 + p) * VTS + n] = vb[p];
    }
    __syncthreads();

    int warp = tid >> 5, lane = tid & 31;
    int gID = lane >> 2, tig = lane & 3;
    int r0 = warp * 16 + gID;
    int r1 = r0 + 8;
    const int HQ = QKB / 2;

    float acc[18][4];
    #pragma unroll
    for (int nt = 0; nt < 18; nt++)
        #pragma unroll
        for (int i = 0; i < 4; i++) acc[nt][i] = 0.f;

    #pragma unroll
    for (int ks = 0; ks < 2; ks++) {
        int kw = ks * 8;
        uint32_t a0 = sqU[r0 * HQ + kw + tig];
        uint32_t a1 = sqU[r1 * HQ + kw + tig];
        uint32_t a2 = sqU[r0 * HQ + kw + 4 + tig];
        uint32_t a3 = sqU[r1 * HQ + kw + 4 + tig];
        #pragma unroll
        for (int nt = 0; nt < 18; nt++) {
            int n = nt * 8 + gID;
            uint32_t b0 = skU[n * HQ + kw + tig];
            uint32_t b1 = skU[n * HQ + kw + 4 + tig];
            asm volatile(
                "mma.sync.aligned.m16n8k16.row.col.f32.bf16.bf16.f32 "
                "{%0,%1,%2,%3}, {%4,%5,%6,%7}, {%8,%9}, {%0,%1,%2,%3};"
                : "+f"(acc[nt][0]), "+f"(acc[nt][1]), "+f"(acc[nt][2]), "+f"(acc[nt][3])
                : "r"(a0), "r"(a1), "r"(a2), "r"(a3), "r"(b0), "r"(b1));
        }
    }

    int ri0 = sri[r0], ri1 = sri[r1];
    float mx0 = -1e30f, mx1 = -1e30f;
    #pragma unroll
    for (int nt = 0; nt < 18; nt++) {
        int j0 = nt * 8 + 2 * tig, j1 = j0 + 1;
        int c0 = scj[j0], c1 = scj[j1];
        acc[nt][0] = acc[nt][0] * scale + sb[ri0 + c0];
        acc[nt][1] = acc[nt][1] * scale + sb[ri0 + c1];
        acc[nt][2] = acc[nt][2] * scale + sb[ri1 + c0];
        acc[nt][3] = acc[nt][3] * scale + sb[ri1 + c1];
        mx0 = fmaxf(mx0, fmaxf(acc[nt][0], acc[nt][1]));
        mx1 = fmaxf(mx1, fmaxf(acc[nt][2], acc[nt][3]));
    }
    mx0 = fmaxf(mx0, __shfl_xor_sync(0xffffffffu, mx0, 1));
    mx0 = fmaxf(mx0, __shfl_xor_sync(0xffffffffu, mx0, 2));
    mx1 = fmaxf(mx1, __shfl_xor_sync(0xffffffffu, mx1, 1));
    mx1 = fmaxf(mx1, __shfl_xor_sync(0xffffffffu, mx1, 2));

    float s0 = 0.f, s1 = 0.f;
    #pragma unroll
    for (int nt = 0; nt < 18; nt++) {
        acc[nt][0] = __expf(acc[nt][0] - mx0);
        acc[nt][1] = __expf(acc[nt][1] - mx0);
        acc[nt][2] = __expf(acc[nt][2] - mx1);
        acc[nt][3] = __expf(acc[nt][3] - mx1);
        s0 += acc[nt][0] + acc[nt][1];
        s1 += acc[nt][2] + acc[nt][3];
    }
    s0 += __shfl_xor_sync(0xffffffffu, s0, 1);
    s0 += __shfl_xor_sync(0xffffffffu, s0, 2);
    s1 += __shfl_xor_sync(0xffffffffu, s1, 1);
    s1 += __shfl_xor_sync(0xffffffffu, s1, 2);
    float inv0 = 1.0f / s0, inv1 = 1.0f / s1;

    float oacc[4][4];
    #pragma unroll
    for (int nt = 0; nt < 4; nt++)
        #pragma unroll
        for (int i = 0; i < 4; i++) oacc[nt][i] = 0.f;

    #pragma unroll
    for (int ks = 0; ks < 9; ks++) {
        uint32_t a0, a1, a2, a3;
        {
            __nv_bfloat162 p0 = __floats2bfloat162_rn(acc[2*ks][0] * inv0, acc[2*ks][1] * inv0);
            __nv_bfloat162 p1 = __floats2bfloat162_rn(acc[2*ks][2] * inv1, acc[2*ks][3] * inv1);
            __nv_bfloat162 p2 = __floats2bfloat162_rn(acc[2*ks+1][0] * inv0, acc[2*ks+1][1] * inv0);
            __nv_bfloat162 p3 = __floats2bfloat162_rn(acc[2*ks+1][2] * inv1, acc[2*ks+1][3] * inv1);
            a0 = *(uint32_t*)&p0;
            a1 = *(uint32_t*)&p1;
            a2 = *(uint32_t*)&p2;
            a3 = *(uint32_t*)&p3;
        }
        int kb = ks * 16 + 2 * tig;
        #pragma unroll
        for (int nt = 0; nt < 4; nt++) {
            int e = nt * 8 + gID;
            uint32_t b0 = svTU[(e * VTS + kb) >> 1];
            uint32_t b1 = svTU[(e * VTS + kb + 8) >> 1];
            asm volatile(
                "mma.sync.aligned.m16n8k16.row.col.f32.bf16.bf16.f32 "
                "{%0,%1,%2,%3}, {%4,%5,%6,%7}, {%8,%9}, {%0,%1,%2,%3};"
                : "+f"(oacc[nt][0]), "+f"(oacc[nt][1]), "+f"(oacc[nt][2]), "+f"(oacc[nt][3])
                : "r"(a0), "r"(a1), "r"(a2), "r"(a3), "r"(b0), "r"(b1));
        }
    }

    #pragma unroll
    for (int nt = 0; nt < 4; nt++) {
        int c = h * HD + nt * 8 + 2 * tig;
        *(__nv_bfloat162*)&g_attn[(base + r0) * (size_t)DIM + c] = __floats2bfloat162_rn(oacc[nt][0], oacc[nt][1]);
        *(__nv_bfloat162*)&g_attn[(base + r1) * (size_t)DIM + c] = __floats2bfloat162_rn(oacc[nt][2], oacc[nt][3]);
    }
}

// ---------------- launch ----------------
extern "C" void kernel_launch(void* const* d_in, const int* in_sizes, int n_in,
                              void* d_out, int out_size) {
    const float* x          = (const float*)d_in[0];
    const float* norm1_g    = (const float*)d_in[1];
    const float* norm1_b    = (const float*)d_in[2];
    const float* qkv_w      = (const float*)d_in[3];
    const float* qkv_b      = (const float*)d_in[4];
    const float* bias_table = (const float*)d_in[5];
    const float* proj_w     = (const float*)d_in[6];
    const float* proj_b     = (const float*)d_in[7];
    const float* norm2_g    = (const float*)d_in[8];
    const float* norm2_b    = (const float*)d_in[9];
    const float* fc1_w      = (const float*)d_in[10];
    const float* fc1_b      = (const float*)d_in[11];
    const float* fc2_w      = (const float*)d_in[12];
    const float* fc2_b      = (const float*)d_in[13];
    float* out = (float*)d_out;

    bf16 *hw, *qkv, *attn, *fc1, *ln2, *wqkv, *wproj, *wfc1, *wfc2;
    float *x2;
    cudaGetSymbolAddress((void**)&hw,    g_hw);
    cudaGetSymbolAddress((void**)&qkv,   g_qkv);
    cudaGetSymbolAddress((void**)&attn,  g_attn);
    cudaGetSymbolAddress((void**)&fc1,   g_fc1);
    cudaGetSymbolAddress((void**)&ln2,   g_ln2);
    cudaGetSymbolAddress((void**)&x2,    g_x2);
    cudaGetSymbolAddress((void**)&wqkv,  g_wqkv);
    cudaGetSymbolAddress((void**)&wproj, g_wproj);
    cudaGetSymbolAddress((void**)&wfc1,  g_wfc1);
    cudaGetSymbolAddress((void**)&wfc2,  g_wfc2);

    cudaFuncSetAttribute(attn_kernel, cudaFuncAttributeMaxDynamicSharedMemorySize, ATTN_SMEM_BYTES);
    cudaFuncSetAttribute(bgemm_kernel<false, false, true,  false>, cudaFuncAttributeMaxDynamicSharedMemorySize, GEMM_SMEM);
    cudaFuncSetAttribute(bgemm_kernel<false, true,  false, true>,  cudaFuncAttributeMaxDynamicSharedMemorySize, GEMM_SMEM);
    cudaFuncSetAttribute(bgemm_kernel<true,  false, true,  false>, cudaFuncAttributeMaxDynamicSharedMemorySize, GEMM_SMEM);
    cudaFuncSetAttribute(bgemm_kernel<false, true,  false, false>, cudaFuncAttributeMaxDynamicSharedMemorySize, GEMM_SMEM);

    // 0) fused weight conversion + bias transpose
    wconv_kernel<<<(NTOT4 + 255)/256, 256>>>(qkv_w, proj_w, fc1_w, fc2_w);
    bt_kernel<<<dim3((TBL + 255)/256, NW*HEADS), 256>>>(bias_table);

    // 1) LN1 + window partition (bf16)
    ln1_kernel<<<MTOK / 8, 256>>>(x, norm1_g, norm1_b);

    // 2) QKV gemm -> bf16
    bgemm_kernel<false, false, true, false><<<dim3(768/128, MTOK/128), 256, GEMM_SMEM>>>(
        hw, wqkv, qkv_b, nullptr, qkv, MTOK, 3 * DIM, DIM);

    // 3) windowed attention -> bf16
    attn_kernel<<<dim3(NW * (BATCH * NLON), HEADS), 288, ATTN_SMEM_BYTES>>>();

    // 4) proj gemm + residual + window-reverse -> x2 (token-ordered float)
    bgemm_kernel<false, true, false, true><<<dim3(DIM/128, MTOK/128), 256, GEMM_SMEM>>>(
        attn, wproj, proj_b, x, x2, MTOK, DIM, DIM);

    // 5) LN2 (token-ordered, bf16 out)
    ln2_kernel<<<MTOK / 8, 256>>>(norm2_g, norm2_b);

    // 6) fc1 gemm + gelu -> bf16
    bgemm_kernel<true, false, true, false><<<dim3(HID/128, MTOK/128), 256, GEMM_SMEM>>>(
        ln2, wfc1, fc1_b, nullptr, fc1, MTOK, HID, DIM);

    // 7) fc2 gemm + residual -> float out
    bgemm_kernel<false, true, false, false><<<dim3(DIM/128, MTOK/128), 256, GEMM_SMEM>>>(
        fc1, wfc2, fc2_b, x2, out, MTOK, DIM, HID);
}

// round 17
// speedup vs baseline: 1.0111x; 1.0111x over previous
#include <cuda_runtime.h>
#include <cuda_bf16.h>
#include <math.h>
#include <stdint.h>

// ---------------- problem constants ----------------
#define DIM   256
#define HEADS 8
#define HD    32
#define PL    8
#define LAT   60
#define LON   120
#define WPL   2
#define WLAT  6
#define WLON  12
#define NTOK  144
#define NPL   (PL/WPL)
#define NLAT  (LAT/WLAT)
#define NLON  (LON/WLON)
#define NW    (NPL*NLAT)     // 40
#define BATCH 2
#define LTOK  (PL*LAT*LON)   // 57600
#define MTOK  (BATCH*LTOK)   // 115200
#define HID   1024
#define TBL   3312

typedef __nv_bfloat16 bf16;

// ---------------- scratch ----------------
__device__ bf16  g_hw  [(size_t)MTOK*DIM];
__device__ bf16  g_qkv [(size_t)MTOK*3*DIM];
__device__ bf16  g_attn[(size_t)MTOK*DIM];
__device__ float g_x2  [(size_t)MTOK*DIM];
__device__ bf16  g_ln2 [(size_t)MTOK*DIM];
__device__ bf16  g_fc1 [(size_t)MTOK*HID];
__device__ bf16  g_wqkv [3*DIM*DIM];
__device__ bf16  g_wproj[DIM*DIM];
__device__ bf16  g_wfc1 [HID*DIM];
__device__ bf16  g_wfc2 [DIM*HID];
__device__ float g_bt  [NW*HEADS*TBL];

// ---------------- helpers ----------------
__device__ __forceinline__ int win_index(int t) {
    int b   = t / LTOK;
    int rem = t - b * LTOK;
    int pl  = rem / (LAT * LON);
    int r2  = rem - pl * (LAT * LON);
    int lat = r2 / LON;
    int lon = r2 - lat * LON;
    int np = pl / WPL,  ip = pl - np * WPL;
    int nl = lat / WLAT, il = lat - nl * WLAT;
    int no = lon / WLON, io = lon - no * WLON;
    int wb = b * NLON + no;
    int w  = np * NLAT + nl;
    int n  = (ip * WLAT + il) * WLON + io;
    return (wb * NW + w) * NTOK + n;
}
__device__ __forceinline__ int inv_win_index(int wi) {
    int n  = wi % NTOK;
    int w  = (wi / NTOK) % NW;
    int wb = wi / (NTOK * NW);
    int b  = wb / NLON, no = wb % NLON;
    int np = w / NLAT,  nl = w % NLAT;
    int ip = n / (WLAT * WLON);
    int il = (n / WLON) % WLAT;
    int io = n % WLON;
    int pl  = np * WPL + ip;
    int lat = nl * WLAT + il;
    int lon = no * WLON + io;
    return b * LTOK + (pl * LAT + lat) * LON + lon;
}
__device__ __forceinline__ void warp_reduce2(float& a, float& b) {
    #pragma unroll
    for (int o = 16; o > 0; o >>= 1) {
        a += __shfl_xor_sync(0xffffffffu, a, o);
        b += __shfl_xor_sync(0xffffffffu, b, o);
    }
}

// ---------------- setup: fused weight conversion + bias transpose ----------------
#define NQ4  (3*DIM*DIM/4)
#define NP4  (DIM*DIM/4)
#define NF14 (HID*DIM/4)
#define NF24 (DIM*HID/4)
#define NTOT4 (NQ4+NP4+NF14+NF24)

__global__ void wconv_kernel(const float* __restrict__ qkv_w,
                             const float* __restrict__ proj_w,
                             const float* __restrict__ fc1_w,
                             const float* __restrict__ fc2_w) {
    int i = blockIdx.x * blockDim.x + threadIdx.x;
    if (i >= NTOT4) return;
    const float* src;
    bf16* dst;
    int j = i;
    if (j < NQ4)                    { src = qkv_w;  dst = g_wqkv;  }
    else if ((j -= NQ4)  < NP4)     { src = proj_w; dst = g_wproj; }
    else if ((j -= NP4)  < NF14)    { src = fc1_w;  dst = g_wfc1;  }
    else { j -= NF14;                 src = fc2_w;  dst = g_wfc2;  }
    float4 v = *(const float4*)&src[j * 4];
    *(__nv_bfloat162*)&dst[j * 4]     = __floats2bfloat162_rn(v.x, v.y);
    *(__nv_bfloat162*)&dst[j * 4 + 2] = __floats2bfloat162_rn(v.z, v.w);
}
__global__ void bt_kernel(const float* __restrict__ src) {
    int c   = blockIdx.y;
    int idx = blockIdx.x * 256 + threadIdx.x;
    if (idx < TBL)
        g_bt[c * TBL + idx] = __ldg(&src[(size_t)idx * (NW * HEADS) + c]);
}

// ---------------- LN1: warp per token, bf16 scatter ----------------
__global__ __launch_bounds__(256)
void ln1_kernel(const float* __restrict__ x,
                const float* __restrict__ g,
                const float* __restrict__ b) {
    int warp = threadIdx.x >> 5, lane = threadIdx.x & 31;
    int t = blockIdx.x * 8 + warp;
    const float4* xr = (const float4*)(x + (size_t)t * DIM);
    float4 u0 = xr[lane], u1 = xr[lane + 32];
    float s = u0.x + u0.y + u0.z + u0.w + u1.x + u1.y + u1.z + u1.w;
    float q = u0.x*u0.x + u0.y*u0.y + u0.z*u0.z + u0.w*u0.w
            + u1.x*u1.x + u1.y*u1.y + u1.z*u1.z + u1.w*u1.w;
    warp_reduce2(s, q);
    float mu  = s * (1.0f / DIM);
    float var = q * (1.0f / DIM) - mu * mu;
    float rs  = rsqrtf(fmaxf(var, 0.f) + 1e-5f);
    float4 g0 = ((const float4*)g)[lane], g1 = ((const float4*)g)[lane + 32];
    float4 b0 = ((const float4*)b)[lane], b1 = ((const float4*)b)[lane + 32];
    int wi = win_index(t);
    __nv_bfloat162* dst = (__nv_bfloat162*)(g_hw + (size_t)wi * DIM);
    dst[lane * 2]          = __floats2bfloat162_rn((u0.x - mu) * rs * g0.x + b0.x,
                                                   (u0.y - mu) * rs * g0.y + b0.y);
    dst[lane * 2 + 1]      = __floats2bfloat162_rn((u0.z - mu) * rs * g0.z + b0.z,
                                                   (u0.w - mu) * rs * g0.w + b0.w);
    dst[64 + lane * 2]     = __floats2bfloat162_rn((u1.x - mu) * rs * g1.x + b1.x,
                                                   (u1.y - mu) * rs * g1.y + b1.y);
    dst[64 + lane * 2 + 1] = __floats2bfloat162_rn((u1.z - mu) * rs * g1.z + b1.z,
                                                   (u1.w - mu) * rs * g1.w + b1.w);
}

// ---------------- LN2 over token-ordered x2 ----------------
__global__ __launch_bounds__(256)
void ln2_kernel(const float* __restrict__ g,
                const float* __restrict__ b) {
    int warp = threadIdx.x >> 5, lane = threadIdx.x & 31;
    int t = blockIdx.x * 8 + warp;
    const float4* xr = (const float4*)(g_x2 + (size_t)t * DIM);
    float4 u0 = xr[lane], u1 = xr[lane + 32];
    float s = u0.x + u0.y + u0.z + u0.w + u1.x + u1.y + u1.z + u1.w;
    float q = u0.x*u0.x + u0.y*u0.y + u0.z*u0.z + u0.w*u0.w
            + u1.x*u1.x + u1.y*u1.y + u1.z*u1.z + u1.w*u1.w;
    warp_reduce2(s, q);
    float mu  = s * (1.0f / DIM);
    float var = q * (1.0f / DIM) - mu * mu;
    float rs  = rsqrtf(fmaxf(var, 0.f) + 1e-5f);
    float4 g0 = ((const float4*)g)[lane], g1 = ((const float4*)g)[lane + 32];
    float4 b0 = ((const float4*)b)[lane], b1 = ((const float4*)b)[lane + 32];
    __nv_bfloat162* dst = (__nv_bfloat162*)(g_ln2 + (size_t)t * DIM);
    dst[lane * 2]          = __floats2bfloat162_rn((u0.x - mu) * rs * g0.x + b0.x,
                                                   (u0.y - mu) * rs * g0.y + b0.y);
    dst[lane * 2 + 1]      = __floats2bfloat162_rn((u0.z - mu) * rs * g0.z + b0.z,
                                                   (u0.w - mu) * rs * g0.w + b0.w);
    dst[64 + lane * 2]     = __floats2bfloat162_rn((u1.x - mu) * rs * g1.x + b1.x,
                                                   (u1.y - mu) * rs * g1.y + b1.y);
    dst[64 + lane * 2 + 1] = __floats2bfloat162_rn((u1.z - mu) * rs * g1.z + b1.z,
                                                   (u1.w - mu) * rs * g1.w + b1.w);
}

// ---------------- bf16 GEMM: BM=BN=128, BK=64, 3-stage, SINGLE sync/iter ----------------
#define BK2  64
#define SAS2 72
#define STG2 (128 * SAS2 * 2)          // 18432 B
#define NSTG 3
#define GEMM_SMEM (2 * NSTG * STG2)    // 110592 B

__device__ __forceinline__ void cp16(uint32_t smem_addr, const void* gmem_src) {
    asm volatile("cp.async.cg.shared.global [%0], [%1], 16;\n" :: "r"(smem_addr), "l"(gmem_src));
}
__device__ __forceinline__ void ldsm_x4(uint32_t& r0, uint32_t& r1, uint32_t& r2, uint32_t& r3,
                                        uint32_t addr) {
    asm volatile("ldmatrix.sync.aligned.m8n8.x4.shared.b16 {%0,%1,%2,%3}, [%4];"
                 : "=r"(r0), "=r"(r1), "=r"(r2), "=r"(r3) : "r"(addr));
}

template<bool GELU, bool RES, bool OBF, bool WREV>
__global__ __launch_bounds__(256, 2)
void bgemm_kernel(const bf16* __restrict__ A,
                  const bf16* __restrict__ W,
                  const float* __restrict__ bias,
                  const float* __restrict__ res,
                  void* __restrict__ Cv,
                  int M, int N, int K) {
    extern __shared__ bf16 smem[];

    int tid  = threadIdx.x;
    int bm   = blockIdx.y * 128;
    int bn   = blockIdx.x * 128;
    int warp = tid >> 5, lane = tid & 31;
    int wm = (warp & 3) * 32;
    int wn = (warp >> 2) * 64;
    int gID = lane >> 2;
    int tig = lane & 3;

    uint32_t aBase = (uint32_t)__cvta_generic_to_shared(&smem[0]);
    uint32_t bBase = aBase + NSTG * STG2;
    int seg = lane >> 3, ri = lane & 7;
    uint32_t aAddr = aBase + (uint32_t)(((wm + (seg & 1) * 8 + ri) * SAS2 + (seg >> 1) * 8) * 2);
    uint32_t bAddr = bBase + (uint32_t)(((wn + (seg >> 1) * 8 + ri) * SAS2 + (seg & 1) * 8) * 2);

    float acc[2][8][4];
    #pragma unroll
    for (int mt = 0; mt < 2; mt++)
        #pragma unroll
        for (int nt = 0; nt < 8; nt++)
            #pragma unroll
            for (int i = 0; i < 4; i++) acc[mt][nt][i] = 0.f;

    int niter = K / BK2;

    auto load_stage = [&](int s, int k0) {
        #pragma unroll
        for (int r4 = 0; r4 < 4; r4++) {
            int idx = tid + r4 * 256;
            int row = idx >> 3, c = idx & 7;
            uint32_t off = (uint32_t)s * STG2 + (uint32_t)((row * SAS2 + c * 8) * 2);
            cp16(aBase + off, &A[(size_t)(bm + row) * K + k0 + c * 8]);
            cp16(bBase + off, &W[(size_t)(bn + row) * K + k0 + c * 8]);
        }
        asm volatile("cp.async.commit_group;\n");
    };

    load_stage(0, 0);
    if (niter > 1) load_stage(1, BK2);

    for (int it = 0; it < niter; it++) {
        int cur = it % NSTG;
        if (it + 1 < niter) asm volatile("cp.async.wait_group 1;\n");
        else                asm volatile("cp.async.wait_group 0;\n");
        __syncthreads();
        // Safe: buffer (it+2)%3 was last read in iter it-1; the barrier above
        // guarantees all threads finished those reads.
        if (it + 2 < niter) load_stage((it + 2) % NSTG, (it + 2) * BK2);

        uint32_t aS = aAddr + (uint32_t)cur * STG2;
        uint32_t bS = bAddr + (uint32_t)cur * STG2;

        #pragma unroll
        for (int ks = 0; ks < 4; ks++) {
            uint32_t ko = ks * 32;
            uint32_t af[2][4];
            ldsm_x4(af[0][0], af[0][1], af[0][2], af[0][3], aS + ko);
            ldsm_x4(af[1][0], af[1][1], af[1][2], af[1][3], aS + 16 * SAS2 * 2 + ko);
            uint32_t bfr[8][2];
            #pragma unroll
            for (int p = 0; p < 4; p++) {
                ldsm_x4(bfr[2*p][0], bfr[2*p][1], bfr[2*p+1][0], bfr[2*p+1][1],
                        bS + (uint32_t)(p * 16 * SAS2 * 2) + ko);
            }
            #pragma unroll
            for (int mt = 0; mt < 2; mt++)
                #pragma unroll
                for (int nt = 0; nt < 8; nt++) {
                    asm volatile(
                        "mma.sync.aligned.m16n8k16.row.col.f32.bf16.bf16.f32 "
                        "{%0,%1,%2,%3}, {%4,%5,%6,%7}, {%8,%9}, {%0,%1,%2,%3};"
                        : "+f"(acc[mt][nt][0]), "+f"(acc[mt][nt][1]),
                          "+f"(acc[mt][nt][2]), "+f"(acc[mt][nt][3])
                        : "r"(af[mt][0]), "r"(af[mt][1]), "r"(af[mt][2]), "r"(af[mt][3]),
                          "r"(bfr[nt][0]), "r"(bfr[nt][1]));
                }
        }
    }

    float* Cf = (float*)Cv;
    bf16*  Cb = (bf16*)Cv;
    #pragma unroll
    for (int mt = 0; mt < 2; mt++) {
        int r0 = bm + wm + mt * 16 + gID;
        int r1 = r0 + 8;
        int t0 = WREV ? inv_win_index(r0) : r0;
        int t1 = WREV ? inv_win_index(r1) : r1;
        #pragma unroll
        for (int nt = 0; nt < 8; nt++) {
            int c = bn + wn + nt * 8 + tig * 2;
            float b0 = bias[c], b1 = bias[c + 1];
            float v00 = acc[mt][nt][0] + b0;
            float v01 = acc[mt][nt][1] + b1;
            float v10 = acc[mt][nt][2] + b0;
            float v11 = acc[mt][nt][3] + b1;
            if (GELU) {
                v00 = 0.5f * v00 * (1.0f + erff(v00 * 0.70710678118654752f));
                v01 = 0.5f * v01 * (1.0f + erff(v01 * 0.70710678118654752f));
                v10 = 0.5f * v10 * (1.0f + erff(v10 * 0.70710678118654752f));
                v11 = 0.5f * v11 * (1.0f + erff(v11 * 0.70710678118654752f));
            }
            size_t o0 = (size_t)t0 * N + c;
            size_t o1 = (size_t)t1 * N + c;
            if (RES) {
                float2 q0 = *(const float2*)&res[o0];
                float2 q1 = *(const float2*)&res[o1];
                v00 += q0.x; v01 += q0.y; v10 += q1.x; v11 += q1.y;
            }
            if (OBF) {
                *(__nv_bfloat162*)&Cb[o0] = __floats2bfloat162_rn(v00, v01);
                *(__nv_bfloat162*)&Cb[o1] = __floats2bfloat162_rn(v10, v11);
            } else {
                *(float2*)&Cf[o0] = make_float2(v00, v01);
                *(float2*)&Cf[o1] = make_float2(v10, v11);
            }
        }
    }
}

// ---------------- windowed attention: bf16 QK^T + register-P bf16 PV ----------------
#define QKB  40
#define VTS  152

#define SQ_B   0
#define SK_B   (SQ_B + NTOK*QKB*2)
#define SVT_B  (SK_B + NTOK*QKB*2)
#define SB_B   (SVT_B + HD*VTS*2)
#define SI_B   (SB_B + TBL*4)
#define ATTN_SMEM_BYTES (SI_B + 288*4)

__global__ __launch_bounds__(288)
void attn_kernel() {
    extern __shared__ char smc[];
    bf16*  sq  = (bf16*)(smc + SQ_B);
    bf16*  sk  = (bf16*)(smc + SK_B);
    bf16*  svT = (bf16*)(smc + SVT_B);
    float* sb  = (float*)(smc + SB_B);
    int*   sri = (int*)(smc + SI_B);
    int*   scj = sri + NTOK;
    const uint32_t* sqU  = (const uint32_t*)sq;
    const uint32_t* skU  = (const uint32_t*)sk;
    const uint32_t* svTU = (const uint32_t*)svT;

    int wg = blockIdx.x;
    int h  = blockIdx.y;
    int wt = wg % NW;
    int tid = threadIdx.x;
    size_t base = (size_t)wg * NTOK;
    const float scale = 0.17677669529663687f;

    if (tid < NTOK) {
        int i = tid;
        sri[i] = (i / 72) * 828 + ((i / 12) % 6) * 23 + (i % 12);
    } else {
        int j = tid - NTOK;
        scj[j] = (j / 72) * 1656 + ((j / 12) % 6) * 138 + (11 - (j % 12));
    }

    {
        const float* bt = g_bt + (size_t)(wt * HEADS + h) * TBL;
        for (int idx = tid; idx < TBL; idx += 288)
            sb[idx] = __ldg(&bt[idx]);
    }

    for (int idx = tid; idx < NTOK * 4; idx += 288) {
        int n = idx >> 2, e8 = (idx & 3) * 8;
        size_t toff = (base + n) * (size_t)(3 * DIM) + h * HD + e8;
        uint4 qr = *(const uint4*)&g_qkv[toff];
        uint4 kr = *(const uint4*)&g_qkv[toff + DIM];
        uint4 vr = *(const uint4*)&g_qkv[toff + 2 * DIM];
        *(uint4*)&sq[n * QKB + e8] = qr;
        *(uint4*)&sk[n * QKB + e8] = kr;
        const bf16* vb = (const bf16*)&vr;
        #pragma unroll
        for (int p = 0; p < 8; p++)
            svT[(e8 + p) * VTS + n] = vb[p];
    }
    __syncthreads();

    int warp = tid >> 5, lane = tid & 31;
    int gID = lane >> 2, tig = lane & 3;
    int r0 = warp * 16 + gID;
    int r1 = r0 + 8;
    const int HQ = QKB / 2;

    float acc[18][4];
    #pragma unroll
    for (int nt = 0; nt < 18; nt++)
        #pragma unroll
        for (int i = 0; i < 4; i++) acc[nt][i] = 0.f;

    #pragma unroll
    for (int ks = 0; ks < 2; ks++) {
        int kw = ks * 8;
        uint32_t a0 = sqU[r0 * HQ + kw + tig];
        uint32_t a1 = sqU[r1 * HQ + kw + tig];
        uint32_t a2 = sqU[r0 * HQ + kw + 4 + tig];
        uint32_t a3 = sqU[r1 * HQ + kw + 4 + tig];
        #pragma unroll
        for (int nt = 0; nt < 18; nt++) {
            int n = nt * 8 + gID;
            uint32_t b0 = skU[n * HQ + kw + tig];
            uint32_t b1 = skU[n * HQ + kw + 4 + tig];
            asm volatile(
                "mma.sync.aligned.m16n8k16.row.col.f32.bf16.bf16.f32 "
                "{%0,%1,%2,%3}, {%4,%5,%6,%7}, {%8,%9}, {%0,%1,%2,%3};"
                : "+f"(acc[nt][0]), "+f"(acc[nt][1]), "+f"(acc[nt][2]), "+f"(acc[nt][3])
                : "r"(a0), "r"(a1), "r"(a2), "r"(a3), "r"(b0), "r"(b1));
        }
    }

    int ri0 = sri[r0], ri1 = sri[r1];
    float mx0 = -1e30f, mx1 = -1e30f;
    #pragma unroll
    for (int nt = 0; nt < 18; nt++) {
        int j0 = nt * 8 + 2 * tig, j1 = j0 + 1;
        int c0 = scj[j0], c1 = scj[j1];
        acc[nt][0] = acc[nt][0] * scale + sb[ri0 + c0];
        acc[nt][1] = acc[nt][1] * scale + sb[ri0 + c1];
        acc[nt][2] = acc[nt][2] * scale + sb[ri1 + c0];
        acc[nt][3] = acc[nt][3] * scale + sb[ri1 + c1];
        mx0 = fmaxf(mx0, fmaxf(acc[nt][0], acc[nt][1]));
        mx1 = fmaxf(mx1, fmaxf(acc[nt][2], acc[nt][3]));
    }
    mx0 = fmaxf(mx0, __shfl_xor_sync(0xffffffffu, mx0, 1));
    mx0 = fmaxf(mx0, __shfl_xor_sync(0xffffffffu, mx0, 2));
    mx1 = fmaxf(mx1, __shfl_xor_sync(0xffffffffu, mx1, 1));
    mx1 = fmaxf(mx1, __shfl_xor_sync(0xffffffffu, mx1, 2));

    float s0 = 0.f, s1 = 0.f;
    #pragma unroll
    for (int nt = 0; nt < 18; nt++) {
        acc[nt][0] = __expf(acc[nt][0] - mx0);
        acc[nt][1] = __expf(acc[nt][1] - mx0);
        acc[nt][2] = __expf(acc[nt][2] - mx1);
        acc[nt][3] = __expf(acc[nt][3] - mx1);
        s0 += acc[nt][0] + acc[nt][1];
        s1 += acc[nt][2] + acc[nt][3];
    }
    s0 += __shfl_xor_sync(0xffffffffu, s0, 1);
    s0 += __shfl_xor_sync(0xffffffffu, s0, 2);
    s1 += __shfl_xor_sync(0xffffffffu, s1, 1);
    s1 += __shfl_xor_sync(0xffffffffu, s1, 2);
    float inv0 = 1.0f / s0, inv1 = 1.0f / s1;

    float oacc[4][4];
    #pragma unroll
    for (int nt = 0; nt < 4; nt++)
        #pragma unroll
        for (int i = 0; i < 4; i++) oacc[nt][i] = 0.f;

    #pragma unroll
    for (int ks = 0; ks < 9; ks++) {
        uint32_t a0, a1, a2, a3;
        {
            __nv_bfloat162 p0 = __floats2bfloat162_rn(acc[2*ks][0] * inv0, acc[2*ks][1] * inv0);
            __nv_bfloat162 p1 = __floats2bfloat162_rn(acc[2*ks][2] * inv1, acc[2*ks][3] * inv1);
            __nv_bfloat162 p2 = __floats2bfloat162_rn(acc[2*ks+1][0] * inv0, acc[2*ks+1][1] * inv0);
            __nv_bfloat162 p3 = __floats2bfloat162_rn(acc[2*ks+1][2] * inv1, acc[2*ks+1][3] * inv1);
            a0 = *(uint32_t*)&p0;
            a1 = *(uint32_t*)&p1;
            a2 = *(uint32_t*)&p2;
            a3 = *(uint32_t*)&p3;
        }
        int kb = ks * 16 + 2 * tig;
        #pragma unroll
        for (int nt = 0; nt < 4; nt++) {
            int e = nt * 8 + gID;
            uint32_t b0 = svTU[(e * VTS + kb) >> 1];
            uint32_t b1 = svTU[(e * VTS + kb + 8) >> 1];
            asm volatile(
                "mma.sync.aligned.m16n8k16.row.col.f32.bf16.bf16.f32 "
                "{%0,%1,%2,%3}, {%4,%5,%6,%7}, {%8,%9}, {%0,%1,%2,%3};"
                : "+f"(oacc[nt][0]), "+f"(oacc[nt][1]), "+f"(oacc[nt][2]), "+f"(oacc[nt][3])
                : "r"(a0), "r"(a1), "r"(a2), "r"(a3), "r"(b0), "r"(b1));
        }
    }

    #pragma unroll
    for (int nt = 0; nt < 4; nt++) {
        int c = h * HD + nt * 8 + 2 * tig;
        *(__nv_bfloat162*)&g_attn[(base + r0) * (size_t)DIM + c] = __floats2bfloat162_rn(oacc[nt][0], oacc[nt][1]);
        *(__nv_bfloat162*)&g_attn[(base + r1) * (size_t)DIM + c] = __floats2bfloat162_rn(oacc[nt][2], oacc[nt][3]);
    }
}

// ---------------- launch ----------------
extern "C" void kernel_launch(void* const* d_in, const int* in_sizes, int n_in,
                              void* d_out, int out_size) {
    const float* x          = (const float*)d_in[0];
    const float* norm1_g    = (const float*)d_in[1];
    const float* norm1_b    = (const float*)d_in[2];
    const float* qkv_w      = (const float*)d_in[3];
    const float* qkv_b      = (const float*)d_in[4];
    const float* bias_table = (const float*)d_in[5];
    const float* proj_w     = (const float*)d_in[6];
    const float* proj_b     = (const float*)d_in[7];
    const float* norm2_g    = (const float*)d_in[8];
    const float* norm2_b    = (const float*)d_in[9];
    const float* fc1_w      = (const float*)d_in[10];
    const float* fc1_b      = (const float*)d_in[11];
    const float* fc2_w      = (const float*)d_in[12];
    const float* fc2_b      = (const float*)d_in[13];
    float* out = (float*)d_out;

    bf16 *hw, *qkv, *attn, *fc1, *ln2, *wqkv, *wproj, *wfc1, *wfc2;
    float *x2;
    cudaGetSymbolAddress((void**)&hw,    g_hw);
    cudaGetSymbolAddress((void**)&qkv,   g_qkv);
    cudaGetSymbolAddress((void**)&attn,  g_attn);
    cudaGetSymbolAddress((void**)&fc1,   g_fc1);
    cudaGetSymbolAddress((void**)&ln2,   g_ln2);
    cudaGetSymbolAddress((void**)&x2,    g_x2);
    cudaGetSymbolAddress((void**)&wqkv,  g_wqkv);
    cudaGetSymbolAddress((void**)&wproj, g_wproj);
    cudaGetSymbolAddress((void**)&wfc1,  g_wfc1);
    cudaGetSymbolAddress((void**)&wfc2,  g_wfc2);

    cudaFuncSetAttribute(attn_kernel, cudaFuncAttributeMaxDynamicSharedMemorySize, ATTN_SMEM_BYTES);
    cudaFuncSetAttribute(bgemm_kernel<false, false, true,  false>, cudaFuncAttributeMaxDynamicSharedMemorySize, GEMM_SMEM);
    cudaFuncSetAttribute(bgemm_kernel<false, true,  false, true>,  cudaFuncAttributeMaxDynamicSharedMemorySize, GEMM_SMEM);
    cudaFuncSetAttribute(bgemm_kernel<true,  false, true,  false>, cudaFuncAttributeMaxDynamicSharedMemorySize, GEMM_SMEM);
    cudaFuncSetAttribute(bgemm_kernel<false, true,  false, false>, cudaFuncAttributeMaxDynamicSharedMemorySize, GEMM_SMEM);

    // 0) fused weight conversion + bias transpose
    wconv_kernel<<<(NTOT4 + 255)/256, 256>>>(qkv_w, proj_w, fc1_w, fc2_w);
    bt_kernel<<<dim3((TBL + 255)/256, NW*HEADS), 256>>>(bias_table);

    // 1) LN1 + window partition (bf16)
    ln1_kernel<<<MTOK / 8, 256>>>(x, norm1_g, norm1_b);

    // 2) QKV gemm -> bf16
    bgemm_kernel<false, false, true, false><<<dim3(768/128, MTOK/128), 256, GEMM_SMEM>>>(
        hw, wqkv, qkv_b, nullptr, qkv, MTOK, 3 * DIM, DIM);

    // 3) windowed attention -> bf16
    attn_kernel<<<dim3(NW * (BATCH * NLON), HEADS), 288, ATTN_SMEM_BYTES>>>();

    // 4) proj gemm + residual + window-reverse -> x2 (token-ordered float)
    bgemm_kernel<false, true, false, true><<<dim3(DIM/128, MTOK/128), 256, GEMM_SMEM>>>(
        attn, wproj, proj_b, x, x2, MTOK, DIM, DIM);

    // 5) LN2 (token-ordered, bf16 out)
    ln2_kernel<<<MTOK / 8, 256>>>(norm2_g, norm2_b);

    // 6) fc1 gemm + gelu -> bf16
    bgemm_kernel<true, false, true, false><<<dim3(HID/128, MTOK/128), 256, GEMM_SMEM>>>(
        ln2, wfc1, fc1_b, nullptr, fc1, MTOK, HID, DIM);

    // 7) fc2 gemm + residual -> float out
    bgemm_kernel<false, true, false, false><<<dim3(DIM/128, MTOK/128), 256, GEMM_SMEM>>>(
        fc1, wfc2, fc2_b, x2, out, MTOK, DIM, HID);
}